// round 12
// baseline (speedup 1.0000x reference)
#include <cuda_runtime.h>
#include <cuda_bf16.h>
#include <cuda_fp16.h>
#include <cstdint>

#define NN 50000
#define NN_PAD 50048          // 391 * 128
#define EE 600000
#define DH 128
#define SCAN_G 49             // 49 * 1024 = 50176 >= NN

// -------- device scratch (no allocations allowed) --------
__device__ __half g_xwh[NN * DH];               // dinv-scaled A@W, fp16
__device__ float g_h[NN * DH];                  // layer-2 output (fp32, for proj)
__device__ float g_dinv[NN];
__device__ int   g_count[NN];                   // statically zero; re-zeroed by k_scan2
__device__ int   g_off[NN + 1];
__device__ int   g_cursor[NN];
__device__ int   g_csr[EE];
__device__ int   g_bsum[SCAN_G];
__device__ int   g_bbase[SCAN_G];
__device__ int   g_tick;
__device__ float g_p[NN * 8];
__device__ __nv_bfloat16 g_ahi[NN_PAD * DH];    // bf16 split of current GEMM input
__device__ __nv_bfloat16 g_alo[NN_PAD * DH];
__device__ __nv_bfloat16 g_b1hi[DH * DH];       // bf16 split of W1^T / W2^T
__device__ __nv_bfloat16 g_b1lo[DH * DH];
__device__ __nv_bfloat16 g_b2hi[DH * DH];
__device__ __nv_bfloat16 g_b2lo[DH * DH];

__device__ __forceinline__ uint32_t smem_u32(const void* p) {
    uint32_t a;
    asm("{ .reg .u64 t; cvta.to.shared.u64 t, %1; cvt.u32.u64 %0, t; }" : "=r"(a) : "l"(p));
    return a;
}

// -------- fused prep: x -> bf16 split, W1/W2 -> bf16 split, edge histogram --------
__global__ void k_prep(const float4* __restrict__ x4,
                       const float* __restrict__ W1, const float* __restrict__ W2,
                       const int4* __restrict__ col4, int E4, int n) {
    int i = blockIdx.x * blockDim.x + threadIdx.x;
    if (i < E4) {                                 // histogram (counts start at zero)
        int4 c = col4[i];
        atomicAdd(&g_count[c.x], 1);
        atomicAdd(&g_count[c.y], 1);
        atomicAdd(&g_count[c.z], 1);
        atomicAdd(&g_count[c.w], 1);
    }
    if (i < 2 * DH * DH) {
        int which = i >> 14;
        int j = i & 16383;
        int nIdx = j >> 7, k = j & 127;
        const float* W = which ? W2 : W1;
        float v = W[k * DH + nIdx];               // transpose: B[n][k] = W[k][n]
        __nv_bfloat16 h = __float2bfloat16(v);
        __nv_bfloat16 l = __float2bfloat16(v - __bfloat162float(h));
        if (which) { g_b2hi[j] = h; g_b2lo[j] = l; }
        else       { g_b1hi[j] = h; g_b1lo[j] = l; }
    }
    if (i >= NN_PAD * 32) return;
    int row = i >> 5;
    float4 v = (row < n) ? x4[i] : make_float4(0.f, 0.f, 0.f, 0.f);
    __nv_bfloat162 h01 = __floats2bfloat162_rn(v.x, v.y);
    __nv_bfloat162 h23 = __floats2bfloat162_rn(v.z, v.w);
    float2 f01 = __bfloat1622float2(h01);
    float2 f23 = __bfloat1622float2(h23);
    __nv_bfloat162 l01 = __floats2bfloat162_rn(v.x - f01.x, v.y - f01.y);
    __nv_bfloat162 l23 = __floats2bfloat162_rn(v.z - f23.x, v.w - f23.y);
    __nv_bfloat162* ah = (__nv_bfloat162*)g_ahi;
    __nv_bfloat162* al = (__nv_bfloat162*)g_alo;
    ah[i * 2] = h01; ah[i * 2 + 1] = h23;
    al[i * 2] = l01; al[i * 2 + 1] = l23;
}

// dinv from counts (runs after prep's histogram, before scan2 zeroes counts)
__global__ void k_dinv(int n) {
    int i = blockIdx.x * blockDim.x + threadIdx.x;
    if (i < n) g_dinv[i] = rsqrtf((float)(g_count[i] + 1));
}

// block sums + last-block scan of the 49 block sums (fused)
__global__ void k_bsum(int n) {
    __shared__ int sh[1024];
    int tid = threadIdx.x;
    int i = blockIdx.x * 1024 + tid;
    sh[tid] = (i < n) ? g_count[i] : 0;
    __syncthreads();
#pragma unroll
    for (int o = 512; o > 0; o >>= 1) {
        if (tid < o) sh[tid] += sh[tid + o];
        __syncthreads();
    }
    if (tid == 0) {
        g_bsum[blockIdx.x] = sh[0];
        __threadfence();
        int t = atomicAdd(&g_tick, 1);
        if (t == SCAN_G - 1) {
            g_tick = 0;                       // reset for next graph replay
            int run = 0;
            for (int b = 0; b < SCAN_G; b++) { g_bbase[b] = run; run += g_bsum[b]; }
        }
    }
}

__global__ void k_scan2(int n) {
    __shared__ int sh[1024];
    int tid = threadIdx.x;
    int i = blockIdx.x * 1024 + tid;
    int v = (i < n) ? g_count[i] : 0;
    sh[tid] = v;
    __syncthreads();
#pragma unroll
    for (int o = 1; o < 1024; o <<= 1) {
        int t = (tid >= o) ? sh[tid - o] : 0;
        __syncthreads();
        sh[tid] += t;
        __syncthreads();
    }
    if (i < n) {
        int excl = g_bbase[blockIdx.x] + sh[tid] - v;
        g_off[i] = excl;
        g_cursor[i] = excl;
        g_count[i] = 0;                       // restore invariant for next replay
        if (i == n - 1) g_off[n] = excl + v;
    }
}

__global__ void k_scatter(const int* __restrict__ ei, int E) {
    int e = blockIdx.x * blockDim.x + threadIdx.x;
    if (e < E) {
        int c = ei[E + e];
        int p = atomicAdd(&g_cursor[c], 1);
        g_csr[p] = ei[e];
    }
}

// ======================= mma.sync (HMMA) GEMM =======================
// xwh[row,:] = fp16( dinv[row] * (A[row,:] @ W) ) via 3-pass bf16 split.
#define SM_AHI  0
#define SM_ALO  32768
#define SM_BHI  65536
#define SM_BLO  98304
#define SM_TOTAL 131072

__device__ __forceinline__ void ldm_x4(uint32_t* r, uint32_t addr) {
    asm volatile("ldmatrix.sync.aligned.m8n8.x4.shared.b16 {%0,%1,%2,%3}, [%4];"
                 : "=r"(r[0]), "=r"(r[1]), "=r"(r[2]), "=r"(r[3]) : "r"(addr) : "memory");
}
__device__ __forceinline__ void mma16816(float* c, const uint32_t* a, const uint32_t* b) {
    asm volatile("mma.sync.aligned.m16n8k16.row.col.f32.bf16.bf16.f32 "
                 "{%0,%1,%2,%3}, {%4,%5,%6,%7}, {%8,%9}, {%0,%1,%2,%3};"
                 : "+f"(c[0]), "+f"(c[1]), "+f"(c[2]), "+f"(c[3])
                 : "r"(a[0]), "r"(a[1]), "r"(a[2]), "r"(a[3]), "r"(b[0]), "r"(b[1]));
}
__device__ __forceinline__ uint32_t sw_off(int row, int chunk) {
    int phys = (chunk & 8) | ((chunk ^ row) & 7);
    return (uint32_t)(row * 256 + phys * 16);
}

__global__ void __launch_bounds__(256, 1) k_gemm_mma(
        __half* __restrict__ C,
        const __nv_bfloat16* __restrict__ bhi,
        const __nv_bfloat16* __restrict__ blo, int n) {
    extern __shared__ char smem[];
    uint32_t sb = smem_u32(smem);
    int tid = threadIdx.x, wid = tid >> 5, lane = tid & 31;
    int row0 = blockIdx.x * 128;

    {
        const __nv_bfloat16* srcs[4] = { g_ahi + (size_t)row0 * DH, g_alo + (size_t)row0 * DH,
                                         bhi, blo };
        const int bases[4] = { SM_AHI, SM_ALO, SM_BHI, SM_BLO };
#pragma unroll
        for (int t4 = 0; t4 < 4; t4++) {
            const uint4* src = (const uint4*)srcs[t4];
#pragma unroll
            for (int j = 0; j < 8; j++) {
                int f = tid + 256 * j;          // 0..2047
                int row = f >> 4;
                int chunk = f & 15;
                *(uint4*)(smem + bases[t4] + sw_off(row, chunk)) = src[row * 16 + chunk];
            }
        }
    }
    __syncthreads();

    int warp_m = wid & 3;
    int warp_n = wid >> 2;
    int lr = lane & 7;
    int rowA0 = warp_m * 32 + ((lane >> 3) & 1) * 8 + lr;
    int aHi = lane >> 4;
    int rowB0 = warp_n * 64 + ((lane >> 4) & 1) * 8 + lr;
    int bHi = (lane >> 3) & 1;

    float c[2][8][4];
#pragma unroll
    for (int mt = 0; mt < 2; mt++)
#pragma unroll
        for (int nt = 0; nt < 8; nt++)
#pragma unroll
            for (int q = 0; q < 4; q++) c[mt][nt][q] = 0.f;

#pragma unroll
    for (int p = 0; p < 3; p++) {
        uint32_t aBase = sb + (p == 2 ? SM_ALO : SM_AHI);
        uint32_t bBase = sb + (p == 1 ? SM_BLO : SM_BHI);
#pragma unroll
        for (int ks = 0; ks < 8; ks++) {
            uint32_t a[2][4];
#pragma unroll
            for (int mt = 0; mt < 2; mt++)
                ldm_x4(a[mt], aBase + sw_off(rowA0 + mt * 16, ks * 2 + aHi));
            uint32_t b[8][2];
#pragma unroll
            for (int nt2 = 0; nt2 < 4; nt2++) {
                uint32_t r[4];
                ldm_x4(r, bBase + sw_off(rowB0 + nt2 * 16, ks * 2 + bHi));
                b[2 * nt2][0] = r[0]; b[2 * nt2][1] = r[1];
                b[2 * nt2 + 1][0] = r[2]; b[2 * nt2 + 1][1] = r[3];
            }
#pragma unroll
            for (int mt = 0; mt < 2; mt++)
#pragma unroll
                for (int nt = 0; nt < 8; nt++)
                    mma16816(c[mt][nt], a[mt], b[nt]);
        }
    }

#pragma unroll
    for (int mt = 0; mt < 2; mt++) {
        int row = row0 + warp_m * 32 + mt * 16 + (lane >> 2);
        int col = warp_n * 64 + (lane & 3) * 2;
        float s0 = (row < n) ? g_dinv[row] : 0.f;
        float s1 = (row + 8 < n) ? g_dinv[row + 8] : 0.f;
#pragma unroll
        for (int nt = 0; nt < 8; nt++) {
            int cc = col + nt * 8;
            if (row < n)
                *(__half2*)&C[(size_t)row * DH + cc] =
                    __floats2half2_rn(c[mt][nt][0] * s0, c[mt][nt][1] * s0);
            if (row + 8 < n)
                *(__half2*)&C[(size_t)(row + 8) * DH + cc] =
                    __floats2half2_rn(c[mt][nt][2] * s1, c[mt][nt][3] * s1);
        }
    }
}

// -------- paired-edge aggregation: warp per node, two 16-lane halves, uint4 loads --------
__device__ __forceinline__ void acc8(float* a, uint4 v) {
    float2 f;
    f = __half22float2(*(__half2*)&v.x); a[0] += f.x; a[1] += f.y;
    f = __half22float2(*(__half2*)&v.y); a[2] += f.x; a[3] += f.y;
    f = __half22float2(*(__half2*)&v.z); a[4] += f.x; a[5] += f.y;
    f = __half22float2(*(__half2*)&v.w); a[6] += f.x; a[7] += f.y;
}

// after return, ALL lanes hold combined sum for features (lane&15)*8 .. +8 (incl. self-loop)
__device__ __forceinline__ void agg_node_pair(const uint4* __restrict__ xwh16, int c,
                                              int lane, float* acc) {
#pragma unroll
    for (int q = 0; q < 8; q++) acc[q] = 0.f;
    int l = lane & 15;
    int half = lane >> 4;
    int s = g_off[c], e = g_off[c + 1];
    int k = s + half;                  // half 0: even slots, half 1: odd slots
    for (; k + 8 <= e; k += 8) {       // 4 iters per half = 8 edges per warp pass
        int r0 = g_csr[k], r1 = g_csr[k + 2], r2 = g_csr[k + 4], r3 = g_csr[k + 6];
        uint4 v0 = xwh16[r0 * 16 + l];
        uint4 v1 = xwh16[r1 * 16 + l];
        uint4 v2 = xwh16[r2 * 16 + l];
        uint4 v3 = xwh16[r3 * 16 + l];
        acc8(acc, v0); acc8(acc, v1); acc8(acc, v2); acc8(acc, v3);
    }
    for (; k < e; k += 2) acc8(acc, xwh16[g_csr[k] * 16 + l]);
    // merge the two halves
#pragma unroll
    for (int q = 0; q < 8; q++) acc[q] += __shfl_xor_sync(0xffffffffu, acc[q], 16);
    // self-loop term (pre-scaled by dinv[c] in GEMM epilogue)
    acc8(acc, xwh16[c * 16 + l]);
}

// layer-1 agg: writes bf16 hi/lo split directly (input of layer-2 GEMM)
__global__ void k_agg_split(const uint4* __restrict__ xwh16, const float4* __restrict__ bias4,
                            int n) {
    int warp = threadIdx.x >> 5, lane = threadIdx.x & 31;
    int c = blockIdx.x * 8 + warp;
    if (c >= n) return;
    float acc[8];
    agg_node_pair(xwh16, c, lane, acc);
    if (lane >= 16) return;
    float di = g_dinv[c];
    float4 bA = bias4[lane * 2], bB = bias4[lane * 2 + 1];
    float o[8];
    o[0] = fmaxf(fmaf(di, acc[0], bA.x), 0.f);
    o[1] = fmaxf(fmaf(di, acc[1], bA.y), 0.f);
    o[2] = fmaxf(fmaf(di, acc[2], bA.z), 0.f);
    o[3] = fmaxf(fmaf(di, acc[3], bA.w), 0.f);
    o[4] = fmaxf(fmaf(di, acc[4], bB.x), 0.f);
    o[5] = fmaxf(fmaf(di, acc[5], bB.y), 0.f);
    o[6] = fmaxf(fmaf(di, acc[6], bB.z), 0.f);
    o[7] = fmaxf(fmaf(di, acc[7], bB.w), 0.f);
    __nv_bfloat162 hi[4], lo[4];
#pragma unroll
    for (int q = 0; q < 4; q++) {
        hi[q] = __floats2bfloat162_rn(o[2 * q], o[2 * q + 1]);
        float2 f = __bfloat1622float2(hi[q]);
        lo[q] = __floats2bfloat162_rn(o[2 * q] - f.x, o[2 * q + 1] - f.y);
    }
    ((uint4*)g_ahi)[c * 16 + lane] = *(uint4*)hi;
    ((uint4*)g_alo)[c * 16 + lane] = *(uint4*)lo;
}

// layer-2 agg: writes fp32 h (consumed by k_proj)
__global__ void k_agg(const uint4* __restrict__ xwh16, const float4* __restrict__ bias4,
                      float4* __restrict__ out4, int n) {
    int warp = threadIdx.x >> 5, lane = threadIdx.x & 31;
    int c = blockIdx.x * 8 + warp;
    if (c >= n) return;
    float acc[8];
    agg_node_pair(xwh16, c, lane, acc);
    if (lane >= 16) return;
    float di = g_dinv[c];
    float4 bA = bias4[lane * 2], bB = bias4[lane * 2 + 1];
    float4 oA, oB;
    oA.x = fmaxf(fmaf(di, acc[0], bA.x), 0.f);
    oA.y = fmaxf(fmaf(di, acc[1], bA.y), 0.f);
    oA.z = fmaxf(fmaf(di, acc[2], bA.z), 0.f);
    oA.w = fmaxf(fmaf(di, acc[3], bA.w), 0.f);
    oB.x = fmaxf(fmaf(di, acc[4], bB.x), 0.f);
    oB.y = fmaxf(fmaf(di, acc[5], bB.y), 0.f);
    oB.z = fmaxf(fmaf(di, acc[6], bB.z), 0.f);
    oB.w = fmaxf(fmaf(di, acc[7], bB.w), 0.f);
    out4[c * 32 + lane * 2] = oA;
    out4[c * 32 + lane * 2 + 1] = oB;
}

// -------- per-node projection --------
__global__ void k_proj(const float* __restrict__ h, const float* __restrict__ Wfc, int n) {
    __shared__ float W[256 * 4];
    int t = threadIdx.x;
    for (int i = t; i < 1024; i += 256) W[i] = Wfc[i];
    __syncthreads();
    int warp = t >> 5, lane = t & 31;
    int node = blockIdx.x * 8 + warp;
    if (node >= n) return;
    float hv[4];
#pragma unroll
    for (int q = 0; q < 4; q++) hv[q] = h[node * 128 + lane + 32 * q];
    float p[8];
#pragma unroll
    for (int j = 0; j < 4; j++) {
        float a = 0.f, b = 0.f;
#pragma unroll
        for (int q = 0; q < 4; q++) {
            int k = lane + 32 * q;
            a = fmaf(hv[q], W[k * 4 + j], a);
            b = fmaf(hv[q], W[(128 + k) * 4 + j], b);
        }
        p[j] = a;
        p[4 + j] = b;
    }
#pragma unroll
    for (int j = 0; j < 8; j++) {
        float v = p[j];
#pragma unroll
        for (int o = 16; o > 0; o >>= 1) v += __shfl_xor_sync(0xffffffffu, v, o);
        if (lane == 0) g_p[node * 8 + j] = v;
    }
}

// -------- edge scoring + log-softmax --------
__global__ void k_edge(const int* __restrict__ ei, const float* __restrict__ bfc,
                       float* __restrict__ out, int E) {
    int e = blockIdx.x * blockDim.x + threadIdx.x;
    if (e >= E) return;
    int r = ei[e];
    int c = ei[E + e];
    float4 pa = *(const float4*)&g_p[r * 8];
    float4 pb = *(const float4*)&g_p[c * 8 + 4];
    float s0 = pa.x + pb.x + bfc[0];
    float s1 = pa.y + pb.y + bfc[1];
    float s2 = pa.z + pb.z + bfc[2];
    float s3 = pa.w + pb.w + bfc[3];
    float m = fmaxf(fmaxf(s0, s1), fmaxf(s2, s3));
    float t0 = expf(s0 - m), t1 = expf(s1 - m), t2 = expf(s2 - m), t3 = expf(s3 - m);
    float l = m + logf(t0 + t1 + t2 + t3);
    *(float4*)&out[e * 4] = make_float4(s0 - l, s1 - l, s2 - l, s3 - l);
}

extern "C" void kernel_launch(void* const* d_in, const int* in_sizes, int n_in,
                              void* d_out, int out_size) {
    const float* x   = (const float*)d_in[0];
    const int*   ei  = (const int*)d_in[1];
    const float* W1  = (const float*)d_in[2];
    const float* b1  = (const float*)d_in[3];
    const float* W2  = (const float*)d_in[4];
    const float* b2  = (const float*)d_in[5];
    const float* Wfc = (const float*)d_in[6];
    const float* bfc = (const float*)d_in[7];
    float* out = (float*)d_out;

    int n = in_sizes[0] / DH;
    int E = in_sizes[1] / 2;
    int E4 = E / 4;

    __half* xwh;
    float* h;
    cudaGetSymbolAddress((void**)&xwh, g_xwh);
    cudaGetSymbolAddress((void**)&h, g_h);
    __nv_bfloat16 *b1hi, *b1lo, *b2hi, *b2lo;
    cudaGetSymbolAddress((void**)&b1hi, g_b1hi);
    cudaGetSymbolAddress((void**)&b1lo, g_b1lo);
    cudaGetSymbolAddress((void**)&b2hi, g_b2hi);
    cudaGetSymbolAddress((void**)&b2lo, g_b2lo);

    static cudaStream_t s2;
    static cudaEvent_t evA, evB;
    static int init_done = 0;
    if (!init_done) {
        cudaFuncSetAttribute(k_gemm_mma, cudaFuncAttributeMaxDynamicSharedMemorySize, SM_TOTAL);
        cudaStreamCreateWithFlags(&s2, cudaStreamNonBlocking);
        cudaEventCreateWithFlags(&evA, cudaEventDisableTiming);
        cudaEventCreateWithFlags(&evB, cudaEventDisableTiming);
        init_done = 1;
    }

    int tb = 256;
    // prep: conversions + histogram (counts are zero by invariant)
    k_prep<<<(NN_PAD * 32 + tb - 1) / tb, tb>>>((const float4*)x, W1, W2,
                                                (const int4*)(ei + E), E4, n);
    // dinv from counts (before scan2 zeroes them; before the fork)
    k_dinv<<<(n + tb - 1) / tb, tb>>>(n);

    // fork: CSR chain on s2 overlaps GEMM1 on stream 0
    cudaEventRecord(evA, 0);
    cudaStreamWaitEvent(s2, evA, 0);
    k_bsum<<<SCAN_G, 1024, 0, s2>>>(n);
    k_scan2<<<SCAN_G, 1024, 0, s2>>>(n);
    k_scatter<<<(E + tb - 1) / tb, tb, 0, s2>>>(ei, E);
    cudaEventRecord(evB, s2);

    k_gemm_mma<<<NN_PAD / 128, 256, SM_TOTAL>>>(xwh, b1hi, b1lo, n);   // overlaps s2 chain

    // join: agg1 needs CSR + GEMM1
    cudaStreamWaitEvent(0, evB, 0);
    k_agg_split<<<(n + 7) / 8, 256>>>((const uint4*)xwh, (const float4*)b1, n);

    // layer 2
    k_gemm_mma<<<NN_PAD / 128, 256, SM_TOTAL>>>(xwh, b2hi, b2lo, n);
    k_agg<<<(n + 7) / 8, 256>>>((const uint4*)xwh, (const float4*)b2, (float4*)h, n);

    // edge classifier
    k_proj<<<(n + 7) / 8, 256>>>(h, Wfc, n);
    k_edge<<<(E + tb - 1) / tb, tb>>>(ei, bfc, out, E);
}

// round 13
// speedup vs baseline: 1.1229x; 1.1229x over previous
#include <cuda_runtime.h>
#include <cuda_bf16.h>
#include <cuda_fp16.h>
#include <cstdint>

#define NN 50000
#define NN_PAD 50048          // 391 * 128
#define EE 600000
#define DH 128
#define SCAN_G 49             // 49 * 1024 = 50176 >= NN

// -------- device scratch (no allocations allowed) --------
__device__ __half g_xwh[NN * DH];               // dinv-scaled A@W, fp16
__device__ __half g_hh[NN * DH];                // layer outputs (fp16)
__device__ float g_dinv[NN];
__device__ int   g_count[NN];                   // statically zero; re-zeroed by k_scan2
__device__ int   g_off[NN + 1];
__device__ int   g_cursor[NN];
__device__ int   g_csr[EE];
__device__ int   g_bsum[SCAN_G];
__device__ int   g_bbase[SCAN_G];
__device__ int   g_tick;
__device__ float g_p[NN * 8];
__device__ __nv_bfloat16 g_b1hi[DH * DH];       // bf16 split of W1^T / W2^T
__device__ __nv_bfloat16 g_b1lo[DH * DH];
__device__ __nv_bfloat16 g_b2hi[DH * DH];
__device__ __nv_bfloat16 g_b2lo[DH * DH];

__device__ __forceinline__ uint32_t smem_u32(const void* p) {
    uint32_t a;
    asm("{ .reg .u64 t; cvta.to.shared.u64 t, %1; cvt.u32.u64 %0, t; }" : "=r"(a) : "l"(p));
    return a;
}

// -------- prep: W1/W2 -> transposed bf16 split + edge histogram --------
__global__ void k_prep(const float* __restrict__ W1, const float* __restrict__ W2,
                       const int4* __restrict__ col4, int E4) {
    int i = blockIdx.x * blockDim.x + threadIdx.x;
    if (i < E4) {                                 // histogram (counts start at zero)
        int4 c = col4[i];
        atomicAdd(&g_count[c.x], 1);
        atomicAdd(&g_count[c.y], 1);
        atomicAdd(&g_count[c.z], 1);
        atomicAdd(&g_count[c.w], 1);
    }
    if (i < 2 * DH * DH) {
        int which = i >> 14;
        int j = i & 16383;
        int nIdx = j >> 7, k = j & 127;
        const float* W = which ? W2 : W1;
        float v = W[k * DH + nIdx];               // transpose: B[n][k] = W[k][n]
        __nv_bfloat16 h = __float2bfloat16(v);
        __nv_bfloat16 l = __float2bfloat16(v - __bfloat162float(h));
        if (which) { g_b2hi[j] = h; g_b2lo[j] = l; }
        else       { g_b1hi[j] = h; g_b1lo[j] = l; }
    }
}

// dinv from counts (runs after prep's histogram, before scan2 zeroes counts)
__global__ void k_dinv(int n) {
    int i = blockIdx.x * blockDim.x + threadIdx.x;
    if (i < n) g_dinv[i] = rsqrtf((float)(g_count[i] + 1));
}

// block sums + last-block scan of the 49 block sums (fused)
__global__ void k_bsum(int n) {
    __shared__ int sh[1024];
    int tid = threadIdx.x;
    int i = blockIdx.x * 1024 + tid;
    sh[tid] = (i < n) ? g_count[i] : 0;
    __syncthreads();
#pragma unroll
    for (int o = 512; o > 0; o >>= 1) {
        if (tid < o) sh[tid] += sh[tid + o];
        __syncthreads();
    }
    if (tid == 0) {
        g_bsum[blockIdx.x] = sh[0];
        __threadfence();
        int t = atomicAdd(&g_tick, 1);
        if (t == SCAN_G - 1) {
            g_tick = 0;                       // reset for next graph replay
            int run = 0;
            for (int b = 0; b < SCAN_G; b++) { g_bbase[b] = run; run += g_bsum[b]; }
        }
    }
}

__global__ void k_scan2(int n) {
    __shared__ int sh[1024];
    int tid = threadIdx.x;
    int i = blockIdx.x * 1024 + tid;
    int v = (i < n) ? g_count[i] : 0;
    sh[tid] = v;
    __syncthreads();
#pragma unroll
    for (int o = 1; o < 1024; o <<= 1) {
        int t = (tid >= o) ? sh[tid - o] : 0;
        __syncthreads();
        sh[tid] += t;
        __syncthreads();
    }
    if (i < n) {
        int excl = g_bbase[blockIdx.x] + sh[tid] - v;
        g_off[i] = excl;
        g_cursor[i] = excl;
        g_count[i] = 0;                       // restore invariant for next replay
        if (i == n - 1) g_off[n] = excl + v;
    }
}

__global__ void k_scatter(const int* __restrict__ ei, int E) {
    int e = blockIdx.x * blockDim.x + threadIdx.x;
    if (e < E) {
        int c = ei[E + e];
        int p = atomicAdd(&g_cursor[c], 1);
        g_csr[p] = ei[e];
    }
}

// ======================= mma.sync (HMMA) GEMM =======================
// xwh[row,:] = fp16( dinv[row] * (A[row,:] @ W) ) via 3-pass bf16 split.
// A-tile split (fp32 or fp16 source -> bf16 hi/lo) done in-kernel.
#define SM_AHI  0
#define SM_ALO  32768
#define SM_BHI  65536
#define SM_BLO  98304
#define SM_TOTAL 131072

__device__ __forceinline__ void ldm_x4(uint32_t* r, uint32_t addr) {
    asm volatile("ldmatrix.sync.aligned.m8n8.x4.shared.b16 {%0,%1,%2,%3}, [%4];"
                 : "=r"(r[0]), "=r"(r[1]), "=r"(r[2]), "=r"(r[3]) : "r"(addr) : "memory");
}
__device__ __forceinline__ void mma16816(float* c, const uint32_t* a, const uint32_t* b) {
    asm volatile("mma.sync.aligned.m16n8k16.row.col.f32.bf16.bf16.f32 "
                 "{%0,%1,%2,%3}, {%4,%5,%6,%7}, {%8,%9}, {%0,%1,%2,%3};"
                 : "+f"(c[0]), "+f"(c[1]), "+f"(c[2]), "+f"(c[3])
                 : "r"(a[0]), "r"(a[1]), "r"(a[2]), "r"(a[3]), "r"(b[0]), "r"(b[1]));
}
__device__ __forceinline__ uint32_t sw_off(int row, int chunk) {
    int phys = (chunk & 8) | ((chunk ^ row) & 7);
    return (uint32_t)(row * 256 + phys * 16);
}

// split 8 fp32 values into bf16 hi/lo 16B chunks
__device__ __forceinline__ void split8(const float* f, uint4& hi, uint4& lo) {
    __nv_bfloat162 h[4], l[4];
#pragma unroll
    for (int q = 0; q < 4; q++) {
        h[q] = __floats2bfloat162_rn(f[2 * q], f[2 * q + 1]);
        float2 r = __bfloat1622float2(h[q]);
        l[q] = __floats2bfloat162_rn(f[2 * q] - r.x, f[2 * q + 1] - r.y);
    }
    hi = *(uint4*)h;
    lo = *(uint4*)l;
}

template <bool F16SRC>
__global__ void __launch_bounds__(256, 1) k_gemm_mma(
        __half* __restrict__ C, const void* __restrict__ Asrc,
        const __nv_bfloat16* __restrict__ bhi,
        const __nv_bfloat16* __restrict__ blo, int n) {
    extern __shared__ char smem[];
    uint32_t sb = smem_u32(smem);
    int tid = threadIdx.x, wid = tid >> 5, lane = tid & 31;
    int row0 = blockIdx.x * 128;

    // ---- A tile: load source, split to bf16 hi/lo in registers ----
#pragma unroll
    for (int j = 0; j < 8; j++) {
        int f = tid + 256 * j;          // 0..2047 chunk-slots (128 rows x 16 chunks)
        int row = f >> 4;
        int chunk = f & 15;
        int gr = row0 + row;
        float fv[8];
        if (F16SRC) {
            uint4 v = make_uint4(0u, 0u, 0u, 0u);
            if (gr < n) v = ((const uint4*)Asrc)[(size_t)gr * 16 + chunk];
            __half2* p = (__half2*)&v;
#pragma unroll
            for (int q = 0; q < 4; q++) {
                float2 r = __half22float2(p[q]);
                fv[2 * q] = r.x; fv[2 * q + 1] = r.y;
            }
        } else {
            float4 a = make_float4(0.f, 0.f, 0.f, 0.f), b = a;
            if (gr < n) {
                a = ((const float4*)Asrc)[(size_t)gr * 32 + chunk * 2];
                b = ((const float4*)Asrc)[(size_t)gr * 32 + chunk * 2 + 1];
            }
            fv[0] = a.x; fv[1] = a.y; fv[2] = a.z; fv[3] = a.w;
            fv[4] = b.x; fv[5] = b.y; fv[6] = b.z; fv[7] = b.w;
        }
        uint4 hi, lo;
        split8(fv, hi, lo);
        uint32_t sw = sw_off(row, chunk);
        *(uint4*)(smem + SM_AHI + sw) = hi;
        *(uint4*)(smem + SM_ALO + sw) = lo;
    }
    // ---- B tiles ----
    {
        const uint4* s1 = (const uint4*)bhi;
        const uint4* s2 = (const uint4*)blo;
#pragma unroll
        for (int j = 0; j < 8; j++) {
            int f = tid + 256 * j;
            int row = f >> 4;
            int chunk = f & 15;
            uint32_t sw = sw_off(row, chunk);
            *(uint4*)(smem + SM_BHI + sw) = s1[row * 16 + chunk];
            *(uint4*)(smem + SM_BLO + sw) = s2[row * 16 + chunk];
        }
    }
    __syncthreads();

    int warp_m = wid & 3;
    int warp_n = wid >> 2;
    int lr = lane & 7;
    int rowA0 = warp_m * 32 + ((lane >> 3) & 1) * 8 + lr;
    int aHi = lane >> 4;
    int rowB0 = warp_n * 64 + ((lane >> 4) & 1) * 8 + lr;
    int bHi = (lane >> 3) & 1;

    float c[2][8][4];
#pragma unroll
    for (int mt = 0; mt < 2; mt++)
#pragma unroll
        for (int nt = 0; nt < 8; nt++)
#pragma unroll
            for (int q = 0; q < 4; q++) c[mt][nt][q] = 0.f;

#pragma unroll
    for (int p = 0; p < 3; p++) {
        uint32_t aBase = sb + (p == 2 ? SM_ALO : SM_AHI);
        uint32_t bBase = sb + (p == 1 ? SM_BLO : SM_BHI);
#pragma unroll
        for (int ks = 0; ks < 8; ks++) {
            uint32_t a[2][4];
#pragma unroll
            for (int mt = 0; mt < 2; mt++)
                ldm_x4(a[mt], aBase + sw_off(rowA0 + mt * 16, ks * 2 + aHi));
            uint32_t b[8][2];
#pragma unroll
            for (int nt2 = 0; nt2 < 4; nt2++) {
                uint32_t r[4];
                ldm_x4(r, bBase + sw_off(rowB0 + nt2 * 16, ks * 2 + bHi));
                b[2 * nt2][0] = r[0]; b[2 * nt2][1] = r[1];
                b[2 * nt2 + 1][0] = r[2]; b[2 * nt2 + 1][1] = r[3];
            }
#pragma unroll
            for (int mt = 0; mt < 2; mt++)
#pragma unroll
                for (int nt = 0; nt < 8; nt++)
                    mma16816(c[mt][nt], a[mt], b[nt]);
        }
    }

#pragma unroll
    for (int mt = 0; mt < 2; mt++) {
        int row = row0 + warp_m * 32 + mt * 16 + (lane >> 2);
        int col = warp_n * 64 + (lane & 3) * 2;
        float s0 = (row < n) ? g_dinv[row] : 0.f;
        float s1 = (row + 8 < n) ? g_dinv[row + 8] : 0.f;
#pragma unroll
        for (int nt = 0; nt < 8; nt++) {
            int cc = col + nt * 8;
            if (row < n)
                *(__half2*)&C[(size_t)row * DH + cc] =
                    __floats2half2_rn(c[mt][nt][0] * s0, c[mt][nt][1] * s0);
            if (row + 8 < n)
                *(__half2*)&C[(size_t)(row + 8) * DH + cc] =
                    __floats2half2_rn(c[mt][nt][2] * s1, c[mt][nt][3] * s1);
        }
    }
}

// -------- aggregation core: one warp per node, fp16 rows (uint2/lane), fp32 accum --------
__device__ __forceinline__ float4 agg_node(const uint2* __restrict__ xwh, int c, int lane) {
    uint2 sv = xwh[c * 32 + lane];                 // self-loop term (pre-scaled by dinv[c])
    float2 a01 = __half22float2(*(__half2*)&sv.x);
    float2 a23 = __half22float2(*(__half2*)&sv.y);
    float4 acc = make_float4(a01.x, a01.y, a23.x, a23.y);
    int s = g_off[c], e = g_off[c + 1];
    int k = s;
    for (; k + 8 <= e; k += 8) {
        int r[8];
#pragma unroll
        for (int j = 0; j < 8; j++) r[j] = g_csr[k + j];
        uint2 v[8];
#pragma unroll
        for (int j = 0; j < 8; j++) v[j] = xwh[r[j] * 32 + lane];
#pragma unroll
        for (int j = 0; j < 8; j++) {
            float2 f01 = __half22float2(*(__half2*)&v[j].x);
            float2 f23 = __half22float2(*(__half2*)&v[j].y);
            acc.x += f01.x; acc.y += f01.y; acc.z += f23.x; acc.w += f23.y;
        }
    }
    for (; k < e; k++) {
        uint2 v = xwh[g_csr[k] * 32 + lane];
        float2 f01 = __half22float2(*(__half2*)&v.x);
        float2 f23 = __half22float2(*(__half2*)&v.y);
        acc.x += f01.x; acc.y += f01.y; acc.z += f23.x; acc.w += f23.y;
    }
    return acc;
}

// both layers: agg + bias + relu, write fp16 out
__global__ void k_agg(const uint2* __restrict__ xwh, const float4* __restrict__ bias4,
                      uint2* __restrict__ out, int n) {
    int warp = threadIdx.x >> 5, lane = threadIdx.x & 31;
    int c = blockIdx.x * 8 + warp;
    if (c >= n) return;
    float4 acc = agg_node(xwh, c, lane);
    float di = g_dinv[c];
    float4 b = bias4[lane];
    float4 o;
    o.x = fmaxf(fmaf(di, acc.x, b.x), 0.f);
    o.y = fmaxf(fmaf(di, acc.y, b.y), 0.f);
    o.z = fmaxf(fmaf(di, acc.z, b.z), 0.f);
    o.w = fmaxf(fmaf(di, acc.w, b.w), 0.f);
    __half2 h01 = __floats2half2_rn(o.x, o.y);
    __half2 h23 = __floats2half2_rn(o.z, o.w);
    uint2 st;
    st.x = *(uint32_t*)&h01;
    st.y = *(uint32_t*)&h23;
    out[c * 32 + lane] = st;
}

// -------- per-node projection (fp16 h input) --------
__global__ void k_proj(const __half* __restrict__ h, const float* __restrict__ Wfc, int n) {
    __shared__ float W[256 * 4];
    int t = threadIdx.x;
    for (int i = t; i < 1024; i += 256) W[i] = Wfc[i];
    __syncthreads();
    int warp = t >> 5, lane = t & 31;
    int node = blockIdx.x * 8 + warp;
    if (node >= n) return;
    float hv[4];
#pragma unroll
    for (int q = 0; q < 4; q++) hv[q] = __half2float(h[node * 128 + lane + 32 * q]);
    float p[8];
#pragma unroll
    for (int j = 0; j < 4; j++) {
        float a = 0.f, b = 0.f;
#pragma unroll
        for (int q = 0; q < 4; q++) {
            int k = lane + 32 * q;
            a = fmaf(hv[q], W[k * 4 + j], a);
            b = fmaf(hv[q], W[(128 + k) * 4 + j], b);
        }
        p[j] = a;
        p[4 + j] = b;
    }
#pragma unroll
    for (int j = 0; j < 8; j++) {
        float v = p[j];
#pragma unroll
        for (int o = 16; o > 0; o >>= 1) v += __shfl_xor_sync(0xffffffffu, v, o);
        if (lane == 0) g_p[node * 8 + j] = v;
    }
}

// -------- edge scoring + log-softmax --------
__global__ void k_edge(const int* __restrict__ ei, const float* __restrict__ bfc,
                       float* __restrict__ out, int E) {
    int e = blockIdx.x * blockDim.x + threadIdx.x;
    if (e >= E) return;
    int r = ei[e];
    int c = ei[E + e];
    float4 pa = *(const float4*)&g_p[r * 8];
    float4 pb = *(const float4*)&g_p[c * 8 + 4];
    float s0 = pa.x + pb.x + bfc[0];
    float s1 = pa.y + pb.y + bfc[1];
    float s2 = pa.z + pb.z + bfc[2];
    float s3 = pa.w + pb.w + bfc[3];
    float m = fmaxf(fmaxf(s0, s1), fmaxf(s2, s3));
    float t0 = expf(s0 - m), t1 = expf(s1 - m), t2 = expf(s2 - m), t3 = expf(s3 - m);
    float l = m + logf(t0 + t1 + t2 + t3);
    *(float4*)&out[e * 4] = make_float4(s0 - l, s1 - l, s2 - l, s3 - l);
}

extern "C" void kernel_launch(void* const* d_in, const int* in_sizes, int n_in,
                              void* d_out, int out_size) {
    const float* x   = (const float*)d_in[0];
    const int*   ei  = (const int*)d_in[1];
    const float* W1  = (const float*)d_in[2];
    const float* b1  = (const float*)d_in[3];
    const float* W2  = (const float*)d_in[4];
    const float* b2  = (const float*)d_in[5];
    const float* Wfc = (const float*)d_in[6];
    const float* bfc = (const float*)d_in[7];
    float* out = (float*)d_out;

    int n = in_sizes[0] / DH;
    int E = in_sizes[1] / 2;
    int E4 = E / 4;

    __half *xwh, *hh;
    cudaGetSymbolAddress((void**)&xwh, g_xwh);
    cudaGetSymbolAddress((void**)&hh, g_hh);
    __nv_bfloat16 *b1hi, *b1lo, *b2hi, *b2lo;
    cudaGetSymbolAddress((void**)&b1hi, g_b1hi);
    cudaGetSymbolAddress((void**)&b1lo, g_b1lo);
    cudaGetSymbolAddress((void**)&b2hi, g_b2hi);
    cudaGetSymbolAddress((void**)&b2lo, g_b2lo);

    static cudaStream_t s2;
    static cudaEvent_t evA, evB;
    static int init_done = 0;
    if (!init_done) {
        cudaFuncSetAttribute(k_gemm_mma<false>, cudaFuncAttributeMaxDynamicSharedMemorySize, SM_TOTAL);
        cudaFuncSetAttribute(k_gemm_mma<true>, cudaFuncAttributeMaxDynamicSharedMemorySize, SM_TOTAL);
        cudaStreamCreateWithFlags(&s2, cudaStreamNonBlocking);
        cudaEventCreateWithFlags(&evA, cudaEventDisableTiming);
        cudaEventCreateWithFlags(&evB, cudaEventDisableTiming);
        init_done = 1;
    }

    int tb = 256;
    // prep: W splits + histogram (counts are zero by invariant)
    int gP = (E4 + tb - 1) / tb;
    if (gP < (2 * DH * DH + tb - 1) / tb) gP = (2 * DH * DH + tb - 1) / tb;
    k_prep<<<gP, tb>>>(W1, W2, (const int4*)(ei + E), E4);
    // dinv from counts (before scan2 zeroes them; before the fork)
    k_dinv<<<(n + tb - 1) / tb, tb>>>(n);

    // fork: CSR chain on s2 overlaps GEMM1 on stream 0
    cudaEventRecord(evA, 0);
    cudaStreamWaitEvent(s2, evA, 0);
    k_bsum<<<SCAN_G, 1024, 0, s2>>>(n);
    k_scan2<<<SCAN_G, 1024, 0, s2>>>(n);
    k_scatter<<<(E + tb - 1) / tb, tb, 0, s2>>>(ei, E);
    cudaEventRecord(evB, s2);

    // GEMM1 reads fp32 x directly (in-kernel split); overlaps s2 chain
    k_gemm_mma<false><<<NN_PAD / 128, 256, SM_TOTAL>>>(xwh, x, b1hi, b1lo, n);

    // join: agg1 needs CSR + GEMM1
    cudaStreamWaitEvent(0, evB, 0);
    k_agg<<<(n + 7) / 8, 256>>>((const uint2*)xwh, (const float4*)b1, (uint2*)hh, n);

    // layer 2: GEMM2 reads fp16 h (in-kernel split)
    k_gemm_mma<true><<<NN_PAD / 128, 256, SM_TOTAL>>>(xwh, hh, b2hi, b2lo, n);
    k_agg<<<(n + 7) / 8, 256>>>((const uint2*)xwh, (const float4*)b2, (uint2*)hh, n);

    // edge classifier
    k_proj<<<(n + 7) / 8, 256>>>(hh, Wfc, n);
    k_edge<<<(E + tb - 1) / tb, tb>>>(ei, bfc, out, E);
}

// round 14
// speedup vs baseline: 1.1676x; 1.0398x over previous
#include <cuda_runtime.h>
#include <cuda_bf16.h>
#include <cuda_fp16.h>
#include <cstdint>

#define NN 50000
#define NN_PAD 50048          // 391 * 128
#define EE 600000
#define DH 128
#define SCAN_G 49             // 49 * 1024 = 50176 >= NN

// -------- device scratch (no allocations allowed) --------
__device__ __half g_xwh[NN * DH];               // dinv-scaled A@W, fp16
__device__ __half g_hh[NN * DH];                // layer outputs (fp16)
__device__ float g_dinv[NN];
__device__ int   g_count[NN];                   // statically zero; re-zeroed by k_scan
__device__ int   g_off[NN + 1];
__device__ int   g_cursor[NN];
__device__ int   g_csr[EE];
__device__ int   g_bsum[SCAN_G];
__device__ int   g_bbase[SCAN_G];
__device__ int   g_tick, g_tick2, g_done;
__device__ float g_p[NN * 8];
__device__ __nv_bfloat16 g_b1hi[DH * DH];       // bf16 split of W1^T
__device__ __nv_bfloat16 g_b1lo[DH * DH];
__device__ __half g_b2hi[DH * DH];              // fp16 split of W2^T
__device__ __half g_b2lo[DH * DH];

__device__ __forceinline__ uint32_t smem_u32(const void* p) {
    uint32_t a;
    asm("{ .reg .u64 t; cvta.to.shared.u64 t, %1; cvt.u32.u64 %0, t; }" : "=r"(a) : "l"(p));
    return a;
}

// -------- prep: W1 -> bf16 split, W2 -> fp16 split (transposed) + edge histogram --------
__global__ void k_prep(const float* __restrict__ W1, const float* __restrict__ W2,
                       const int4* __restrict__ col4, int E4) {
    int i = blockIdx.x * blockDim.x + threadIdx.x;
    if (i < E4) {                                 // histogram (counts start at zero)
        int4 c = col4[i];
        atomicAdd(&g_count[c.x], 1);
        atomicAdd(&g_count[c.y], 1);
        atomicAdd(&g_count[c.z], 1);
        atomicAdd(&g_count[c.w], 1);
    }
    if (i < 2 * DH * DH) {
        int which = i >> 14;
        int j = i & 16383;
        int nIdx = j >> 7, k = j & 127;
        if (which) {
            float v = W2[k * DH + nIdx];          // transpose
            __half h = __float2half_rn(v);
            g_b2hi[j] = h;
            g_b2lo[j] = __float2half_rn(v - __half2float(h));
        } else {
            float v = W1[k * DH + nIdx];
            __nv_bfloat16 h = __float2bfloat16(v);
            g_b1hi[j] = h;
            g_b1lo[j] = __float2bfloat16(v - __bfloat162float(h));
        }
    }
}

// dinv from counts (runs after prep's histogram, before k_scan zeroes counts)
__global__ void k_dinv(int n) {
    int i = blockIdx.x * blockDim.x + threadIdx.x;
    if (i < n) g_dinv[i] = rsqrtf((float)(g_count[i] + 1));
}

// fused scan: block sums + cross-block base (spin) + local scan + cursor init + count reset
__global__ void k_scan(int n) {
    __shared__ int sh[1024];
    __shared__ int base_sh;
    int tid = threadIdx.x, b = blockIdx.x;
    int i = b * 1024 + tid;
    int v = (i < n) ? g_count[i] : 0;
    sh[tid] = v;
    __syncthreads();
#pragma unroll
    for (int o = 512; o > 0; o >>= 1) {
        if (tid < o) sh[tid] += sh[tid + o];
        __syncthreads();
    }
    if (tid == 0) {
        g_bsum[b] = sh[0];
        __threadfence();
        int t = atomicAdd(&g_tick, 1);
        if (t == SCAN_G - 1) {                 // last arriver computes bases
            int run = 0;
            for (int bb = 0; bb < SCAN_G; bb++) { g_bbase[bb] = run; run += g_bsum[bb]; }
            __threadfence();
            atomicExch(&g_done, 1);
        }
    }
    __syncthreads();
    // local inclusive scan (overlaps other blocks' publish)
    sh[tid] = v;
    __syncthreads();
#pragma unroll
    for (int o = 1; o < 1024; o <<= 1) {
        int t = (tid >= o) ? sh[tid - o] : 0;
        __syncthreads();
        sh[tid] += t;
        __syncthreads();
    }
    if (tid == 0) {
        while (atomicAdd(&g_done, 0) == 0) { }
        base_sh = g_bbase[b];
    }
    __syncthreads();
    if (i < n) {
        int excl = base_sh + sh[tid] - v;
        g_off[i] = excl;
        g_cursor[i] = excl;
        g_count[i] = 0;                       // restore invariant for next replay
        if (i == n - 1) g_off[n] = excl + v;
    }
    __syncthreads();
    if (tid == 0) {                           // departure: last block resets sync state
        int t2 = atomicAdd(&g_tick2, 1);
        if (t2 == SCAN_G - 1) { g_tick = 0; g_tick2 = 0; g_done = 0; }
    }
}

__global__ void k_scatter(const int* __restrict__ ei, int E) {
    int e = blockIdx.x * blockDim.x + threadIdx.x;
    if (e < E) {
        int c = ei[E + e];
        int p = atomicAdd(&g_cursor[c], 1);
        g_csr[p] = ei[e];
    }
}

// ======================= mma.sync (HMMA) GEMMs =======================
#define SM_AHI  0
#define SM_ALO  32768
#define SM_BHI  65536
#define SM_BLO  98304
#define SM_TOTAL 131072
// gemm2 (fp16, no A split): A at 0, BHI 32768, BLO 65536
#define SM2_TOTAL 98304

__device__ __forceinline__ void ldm_x4(uint32_t* r, uint32_t addr) {
    asm volatile("ldmatrix.sync.aligned.m8n8.x4.shared.b16 {%0,%1,%2,%3}, [%4];"
                 : "=r"(r[0]), "=r"(r[1]), "=r"(r[2]), "=r"(r[3]) : "r"(addr) : "memory");
}
__device__ __forceinline__ void mma_bf16(float* c, const uint32_t* a, const uint32_t* b) {
    asm volatile("mma.sync.aligned.m16n8k16.row.col.f32.bf16.bf16.f32 "
                 "{%0,%1,%2,%3}, {%4,%5,%6,%7}, {%8,%9}, {%0,%1,%2,%3};"
                 : "+f"(c[0]), "+f"(c[1]), "+f"(c[2]), "+f"(c[3])
                 : "r"(a[0]), "r"(a[1]), "r"(a[2]), "r"(a[3]), "r"(b[0]), "r"(b[1]));
}
__device__ __forceinline__ void mma_f16(float* c, const uint32_t* a, const uint32_t* b) {
    asm volatile("mma.sync.aligned.m16n8k16.row.col.f32.f16.f16.f32 "
                 "{%0,%1,%2,%3}, {%4,%5,%6,%7}, {%8,%9}, {%0,%1,%2,%3};"
                 : "+f"(c[0]), "+f"(c[1]), "+f"(c[2]), "+f"(c[3])
                 : "r"(a[0]), "r"(a[1]), "r"(a[2]), "r"(a[3]), "r"(b[0]), "r"(b[1]));
}
__device__ __forceinline__ uint32_t sw_off(int row, int chunk) {
    int phys = (chunk & 8) | ((chunk ^ row) & 7);
    return (uint32_t)(row * 256 + phys * 16);
}

// split 8 fp32 values into bf16 hi/lo 16B chunks
__device__ __forceinline__ void split8(const float* f, uint4& hi, uint4& lo) {
    __nv_bfloat162 h[4], l[4];
#pragma unroll
    for (int q = 0; q < 4; q++) {
        h[q] = __floats2bfloat162_rn(f[2 * q], f[2 * q + 1]);
        float2 r = __bfloat1622float2(h[q]);
        l[q] = __floats2bfloat162_rn(f[2 * q] - r.x, f[2 * q + 1] - r.y);
    }
    hi = *(uint4*)h;
    lo = *(uint4*)l;
}

// layer-1 GEMM: fp32 A, 3-pass bf16 split (in-kernel)
__global__ void __launch_bounds__(256, 1) k_gemm1(
        __half* __restrict__ C, const float* __restrict__ Asrc,
        const __nv_bfloat16* __restrict__ bhi,
        const __nv_bfloat16* __restrict__ blo, int n) {
    extern __shared__ char smem[];
    uint32_t sb = smem_u32(smem);
    int tid = threadIdx.x, wid = tid >> 5, lane = tid & 31;
    int row0 = blockIdx.x * 128;

#pragma unroll
    for (int j = 0; j < 8; j++) {
        int f = tid + 256 * j;
        int row = f >> 4;
        int chunk = f & 15;
        int gr = row0 + row;
        float fv[8];
        float4 a = make_float4(0.f, 0.f, 0.f, 0.f), b = a;
        if (gr < n) {
            a = ((const float4*)Asrc)[(size_t)gr * 32 + chunk * 2];
            b = ((const float4*)Asrc)[(size_t)gr * 32 + chunk * 2 + 1];
        }
        fv[0] = a.x; fv[1] = a.y; fv[2] = a.z; fv[3] = a.w;
        fv[4] = b.x; fv[5] = b.y; fv[6] = b.z; fv[7] = b.w;
        uint4 hi, lo;
        split8(fv, hi, lo);
        uint32_t sw = sw_off(row, chunk);
        *(uint4*)(smem + SM_AHI + sw) = hi;
        *(uint4*)(smem + SM_ALO + sw) = lo;
    }
    {
        const uint4* s1 = (const uint4*)bhi;
        const uint4* s2 = (const uint4*)blo;
#pragma unroll
        for (int j = 0; j < 8; j++) {
            int f = tid + 256 * j;
            int row = f >> 4;
            int chunk = f & 15;
            uint32_t sw = sw_off(row, chunk);
            *(uint4*)(smem + SM_BHI + sw) = s1[row * 16 + chunk];
            *(uint4*)(smem + SM_BLO + sw) = s2[row * 16 + chunk];
        }
    }
    __syncthreads();

    int warp_m = wid & 3;
    int warp_n = wid >> 2;
    int lr = lane & 7;
    int rowA0 = warp_m * 32 + ((lane >> 3) & 1) * 8 + lr;
    int aHi = lane >> 4;
    int rowB0 = warp_n * 64 + ((lane >> 4) & 1) * 8 + lr;
    int bHi = (lane >> 3) & 1;

    float c[2][8][4];
#pragma unroll
    for (int mt = 0; mt < 2; mt++)
#pragma unroll
        for (int nt = 0; nt < 8; nt++)
#pragma unroll
            for (int q = 0; q < 4; q++) c[mt][nt][q] = 0.f;

#pragma unroll
    for (int p = 0; p < 3; p++) {
        uint32_t aBase = sb + (p == 2 ? SM_ALO : SM_AHI);
        uint32_t bBase = sb + (p == 1 ? SM_BLO : SM_BHI);
#pragma unroll
        for (int ks = 0; ks < 8; ks++) {
            uint32_t a[2][4];
#pragma unroll
            for (int mt = 0; mt < 2; mt++)
                ldm_x4(a[mt], aBase + sw_off(rowA0 + mt * 16, ks * 2 + aHi));
            uint32_t b[8][2];
#pragma unroll
            for (int nt2 = 0; nt2 < 4; nt2++) {
                uint32_t r[4];
                ldm_x4(r, bBase + sw_off(rowB0 + nt2 * 16, ks * 2 + bHi));
                b[2 * nt2][0] = r[0]; b[2 * nt2][1] = r[1];
                b[2 * nt2 + 1][0] = r[2]; b[2 * nt2 + 1][1] = r[3];
            }
#pragma unroll
            for (int mt = 0; mt < 2; mt++)
#pragma unroll
                for (int nt = 0; nt < 8; nt++)
                    mma_bf16(c[mt][nt], a[mt], b[nt]);
        }
    }

#pragma unroll
    for (int mt = 0; mt < 2; mt++) {
        int row = row0 + warp_m * 32 + mt * 16 + (lane >> 2);
        int col = warp_n * 64 + (lane & 3) * 2;
        float s0 = (row < n) ? g_dinv[row] : 0.f;
        float s1 = (row + 8 < n) ? g_dinv[row + 8] : 0.f;
#pragma unroll
        for (int nt = 0; nt < 8; nt++) {
            int cc = col + nt * 8;
            if (row < n)
                *(__half2*)&C[(size_t)row * DH + cc] =
                    __floats2half2_rn(c[mt][nt][0] * s0, c[mt][nt][1] * s0);
            if (row + 8 < n)
                *(__half2*)&C[(size_t)(row + 8) * DH + cc] =
                    __floats2half2_rn(c[mt][nt][2] * s1, c[mt][nt][3] * s1);
        }
    }
}

// layer-2 GEMM: fp16 A (exact), 2-pass fp16 W split
__global__ void __launch_bounds__(256, 1) k_gemm2(
        __half* __restrict__ C, const __half* __restrict__ Asrc,
        const __half* __restrict__ bhi, const __half* __restrict__ blo, int n) {
    extern __shared__ char smem[];
    uint32_t sb = smem_u32(smem);
    int tid = threadIdx.x, wid = tid >> 5, lane = tid & 31;
    int row0 = blockIdx.x * 128;

    {
        const uint4* sa = (const uint4*)Asrc;
        const uint4* s1 = (const uint4*)bhi;
        const uint4* s2 = (const uint4*)blo;
#pragma unroll
        for (int j = 0; j < 8; j++) {
            int f = tid + 256 * j;
            int row = f >> 4;
            int chunk = f & 15;
            int gr = row0 + row;
            uint4 av = make_uint4(0u, 0u, 0u, 0u);
            if (gr < n) av = sa[(size_t)gr * 16 + chunk];
            uint32_t sw = sw_off(row, chunk);
            *(uint4*)(smem + 0 + sw) = av;
            *(uint4*)(smem + 32768 + sw) = s1[row * 16 + chunk];
            *(uint4*)(smem + 65536 + sw) = s2[row * 16 + chunk];
        }
    }
    __syncthreads();

    int warp_m = wid & 3;
    int warp_n = wid >> 2;
    int lr = lane & 7;
    int rowA0 = warp_m * 32 + ((lane >> 3) & 1) * 8 + lr;
    int aHi = lane >> 4;
    int rowB0 = warp_n * 64 + ((lane >> 4) & 1) * 8 + lr;
    int bHi = (lane >> 3) & 1;

    float c[2][8][4];
#pragma unroll
    for (int mt = 0; mt < 2; mt++)
#pragma unroll
        for (int nt = 0; nt < 8; nt++)
#pragma unroll
            for (int q = 0; q < 4; q++) c[mt][nt][q] = 0.f;

#pragma unroll
    for (int p = 0; p < 2; p++) {
        uint32_t aBase = sb;
        uint32_t bBase = sb + (p == 1 ? 65536 : 32768);
#pragma unroll
        for (int ks = 0; ks < 8; ks++) {
            uint32_t a[2][4];
#pragma unroll
            for (int mt = 0; mt < 2; mt++)
                ldm_x4(a[mt], aBase + sw_off(rowA0 + mt * 16, ks * 2 + aHi));
            uint32_t b[8][2];
#pragma unroll
            for (int nt2 = 0; nt2 < 4; nt2++) {
                uint32_t r[4];
                ldm_x4(r, bBase + sw_off(rowB0 + nt2 * 16, ks * 2 + bHi));
                b[2 * nt2][0] = r[0]; b[2 * nt2][1] = r[1];
                b[2 * nt2 + 1][0] = r[2]; b[2 * nt2 + 1][1] = r[3];
            }
#pragma unroll
            for (int mt = 0; mt < 2; mt++)
#pragma unroll
                for (int nt = 0; nt < 8; nt++)
                    mma_f16(c[mt][nt], a[mt], b[nt]);
        }
    }

#pragma unroll
    for (int mt = 0; mt < 2; mt++) {
        int row = row0 + warp_m * 32 + mt * 16 + (lane >> 2);
        int col = warp_n * 64 + (lane & 3) * 2;
        float s0 = (row < n) ? g_dinv[row] : 0.f;
        float s1 = (row + 8 < n) ? g_dinv[row + 8] : 0.f;
#pragma unroll
        for (int nt = 0; nt < 8; nt++) {
            int cc = col + nt * 8;
            if (row < n)
                *(__half2*)&C[(size_t)row * DH + cc] =
                    __floats2half2_rn(c[mt][nt][0] * s0, c[mt][nt][1] * s0);
            if (row + 8 < n)
                *(__half2*)&C[(size_t)(row + 8) * DH + cc] =
                    __floats2half2_rn(c[mt][nt][2] * s1, c[mt][nt][3] * s1);
        }
    }
}

// -------- aggregation core: one warp per node, fp16 rows (uint2/lane), fp32 accum --------
__device__ __forceinline__ float4 agg_node(const uint2* __restrict__ xwh, int c, int lane) {
    uint2 sv = xwh[c * 32 + lane];                 // self-loop term (pre-scaled by dinv[c])
    float2 a01 = __half22float2(*(__half2*)&sv.x);
    float2 a23 = __half22float2(*(__half2*)&sv.y);
    float4 acc = make_float4(a01.x, a01.y, a23.x, a23.y);
    int s = g_off[c], e = g_off[c + 1];
    int k = s;
    for (; k + 8 <= e; k += 8) {
        int r[8];
#pragma unroll
        for (int j = 0; j < 8; j++) r[j] = g_csr[k + j];
        uint2 v[8];
#pragma unroll
        for (int j = 0; j < 8; j++) v[j] = xwh[r[j] * 32 + lane];
#pragma unroll
        for (int j = 0; j < 8; j++) {
            float2 f01 = __half22float2(*(__half2*)&v[j].x);
            float2 f23 = __half22float2(*(__half2*)&v[j].y);
            acc.x += f01.x; acc.y += f01.y; acc.z += f23.x; acc.w += f23.y;
        }
    }
    for (; k < e; k++) {
        uint2 v = xwh[g_csr[k] * 32 + lane];
        float2 f01 = __half22float2(*(__half2*)&v.x);
        float2 f23 = __half22float2(*(__half2*)&v.y);
        acc.x += f01.x; acc.y += f01.y; acc.z += f23.x; acc.w += f23.y;
    }
    return acc;
}

// both layers: agg + bias + relu, write fp16 out
__global__ void k_agg(const uint2* __restrict__ xwh, const float4* __restrict__ bias4,
                      uint2* __restrict__ out, int n) {
    int warp = threadIdx.x >> 5, lane = threadIdx.x & 31;
    int c = blockIdx.x * 8 + warp;
    if (c >= n) return;
    float4 acc = agg_node(xwh, c, lane);
    float di = g_dinv[c];
    float4 b = bias4[lane];
    float4 o;
    o.x = fmaxf(fmaf(di, acc.x, b.x), 0.f);
    o.y = fmaxf(fmaf(di, acc.y, b.y), 0.f);
    o.z = fmaxf(fmaf(di, acc.z, b.z), 0.f);
    o.w = fmaxf(fmaf(di, acc.w, b.w), 0.f);
    __half2 h01 = __floats2half2_rn(o.x, o.y);
    __half2 h23 = __floats2half2_rn(o.z, o.w);
    uint2 st;
    st.x = *(uint32_t*)&h01;
    st.y = *(uint32_t*)&h23;
    out[c * 32 + lane] = st;
}

// -------- per-node projection (fp16 h input) --------
__global__ void k_proj(const __half* __restrict__ h, const float* __restrict__ Wfc, int n) {
    __shared__ float W[256 * 4];
    int t = threadIdx.x;
    for (int i = t; i < 1024; i += 256) W[i] = Wfc[i];
    __syncthreads();
    int warp = t >> 5, lane = t & 31;
    int node = blockIdx.x * 8 + warp;
    if (node >= n) return;
    float hv[4];
#pragma unroll
    for (int q = 0; q < 4; q++) hv[q] = __half2float(h[node * 128 + lane + 32 * q]);
    float p[8];
#pragma unroll
    for (int j = 0; j < 4; j++) {
        float a = 0.f, b = 0.f;
#pragma unroll
        for (int q = 0; q < 4; q++) {
            int k = lane + 32 * q;
            a = fmaf(hv[q], W[k * 4 + j], a);
            b = fmaf(hv[q], W[(128 + k) * 4 + j], b);
        }
        p[j] = a;
        p[4 + j] = b;
    }
#pragma unroll
    for (int j = 0; j < 8; j++) {
        float v = p[j];
#pragma unroll
        for (int o = 16; o > 0; o >>= 1) v += __shfl_xor_sync(0xffffffffu, v, o);
        if (lane == 0) g_p[node * 8 + j] = v;
    }
}

// -------- edge scoring + log-softmax (fast math) --------
__global__ void k_edge(const int* __restrict__ ei, const float* __restrict__ bfc,
                       float* __restrict__ out, int E) {
    int e = blockIdx.x * blockDim.x + threadIdx.x;
    if (e >= E) return;
    int r = ei[e];
    int c = ei[E + e];
    float4 pa = *(const float4*)&g_p[r * 8];
    float4 pb = *(const float4*)&g_p[c * 8 + 4];
    float s0 = pa.x + pb.x + bfc[0];
    float s1 = pa.y + pb.y + bfc[1];
    float s2 = pa.z + pb.z + bfc[2];
    float s3 = pa.w + pb.w + bfc[3];
    float m = fmaxf(fmaxf(s0, s1), fmaxf(s2, s3));
    float t0 = __expf(s0 - m), t1 = __expf(s1 - m), t2 = __expf(s2 - m), t3 = __expf(s3 - m);
    float l = m + __logf(t0 + t1 + t2 + t3);
    *(float4*)&out[e * 4] = make_float4(s0 - l, s1 - l, s2 - l, s3 - l);
}

extern "C" void kernel_launch(void* const* d_in, const int* in_sizes, int n_in,
                              void* d_out, int out_size) {
    const float* x   = (const float*)d_in[0];
    const int*   ei  = (const int*)d_in[1];
    const float* W1  = (const float*)d_in[2];
    const float* b1  = (const float*)d_in[3];
    const float* W2  = (const float*)d_in[4];
    const float* b2  = (const float*)d_in[5];
    const float* Wfc = (const float*)d_in[6];
    const float* bfc = (const float*)d_in[7];
    float* out = (float*)d_out;

    int n = in_sizes[0] / DH;
    int E = in_sizes[1] / 2;
    int E4 = E / 4;

    __half *xwh, *hh;
    cudaGetSymbolAddress((void**)&xwh, g_xwh);
    cudaGetSymbolAddress((void**)&hh, g_hh);
    __nv_bfloat16 *b1hi, *b1lo;
    __half *b2hi, *b2lo;
    cudaGetSymbolAddress((void**)&b1hi, g_b1hi);
    cudaGetSymbolAddress((void**)&b1lo, g_b1lo);
    cudaGetSymbolAddress((void**)&b2hi, g_b2hi);
    cudaGetSymbolAddress((void**)&b2lo, g_b2lo);

    static cudaStream_t s2;
    static cudaEvent_t evA, evB;
    static int init_done = 0;
    if (!init_done) {
        cudaFuncSetAttribute(k_gemm1, cudaFuncAttributeMaxDynamicSharedMemorySize, SM_TOTAL);
        cudaFuncSetAttribute(k_gemm2, cudaFuncAttributeMaxDynamicSharedMemorySize, SM2_TOTAL);
        cudaStreamCreateWithFlags(&s2, cudaStreamNonBlocking);
        cudaEventCreateWithFlags(&evA, cudaEventDisableTiming);
        cudaEventCreateWithFlags(&evB, cudaEventDisableTiming);
        init_done = 1;
    }

    int tb = 256;
    // prep: W splits + histogram (counts are zero by invariant)
    int gP = (E4 + tb - 1) / tb;
    if (gP < (2 * DH * DH + tb - 1) / tb) gP = (2 * DH * DH + tb - 1) / tb;
    k_prep<<<gP, tb>>>(W1, W2, (const int4*)(ei + E), E4);
    // dinv from counts (before k_scan zeroes them; before the fork)
    k_dinv<<<(n + tb - 1) / tb, tb>>>(n);

    // fork: CSR chain on s2 overlaps GEMM1 on stream 0
    cudaEventRecord(evA, 0);
    cudaStreamWaitEvent(s2, evA, 0);
    k_scan<<<SCAN_G, 1024, 0, s2>>>(n);
    k_scatter<<<(E + tb - 1) / tb, tb, 0, s2>>>(ei, E);
    cudaEventRecord(evB, s2);

    // GEMM1 reads fp32 x directly (in-kernel bf16 split); overlaps s2 chain
    k_gemm1<<<NN_PAD / 128, 256, SM_TOTAL>>>(xwh, x, b1hi, b1lo, n);

    // join: agg1 needs CSR + GEMM1
    cudaStreamWaitEvent(0, evB, 0);
    k_agg<<<(n + 7) / 8, 256>>>((const uint2*)xwh, (const float4*)b1, (uint2*)hh, n);

    // layer 2: GEMM2 reads fp16 h (exact, 2-pass fp16 W split)
    k_gemm2<<<NN_PAD / 128, 256, SM2_TOTAL>>>(xwh, hh, b2hi, b2lo, n);
    k_agg<<<(n + 7) / 8, 256>>>((const uint2*)xwh, (const float4*)b2, (uint2*)hh, n);

    // edge classifier
    k_proj<<<(n + 7) / 8, 256>>>(hh, Wfc, n);
    k_edge<<<(E + tb - 1) / tb, tb>>>(ei, bfc, out, E);
}